// round 10
// baseline (speedup 1.0000x reference)
#include <cuda_runtime.h>
#include <cuda_bf16.h>
#include <cuda_fp16.h>
#include <cstdint>
#include <cstddef>

// ---------------------------------------------------------------- constants
#define DQ   128          // head dim d == projection dim m
#define QN   512          // queries
#define NKEY 131072       // keys
#define KH   256          // fp16 halves per augmented row: [0:128) mse*vn, [128:256) sign*c
#define NCHUNK 4          // 4 x 64-col K chunks (main gemm)
#define TM 128
#define TN 128
#define EPSV 1e-8f
// sqrt(pi/2)/128
#define SCALEC 0.009791516697777347f

// ---------------------------------------------------------------- scratch
__device__ uint4 g_Kaug4[(size_t)NKEY * KH / 8];        // 64 MB fp16
__device__ uint4 g_Qaug4[(size_t)QN * KH / 8];          // 256 KB fp16
__device__ uint4 g_Sh4[DQ * DQ / 8];                    // S hi fp16, [t][j]
__device__ uint4 g_Sl4[DQ * DQ / 8];                    // S lo fp16, [t][j]

// ---------------------------------------------------------------- ptx utils
__device__ __forceinline__ uint32_t smem_u32(const void* p) {
    uint32_t a;
    asm("{ .reg .u64 tmp; cvta.to.shared.u64 tmp, %1; cvt.u32.u64 %0, tmp; }" : "=r"(a) : "l"(p));
    return a;
}
__device__ __forceinline__ uint32_t h2pack(float a, float b) {
    __half2 h = __floats2half2_rn(a, b);   // a -> low half (memory-first)
    return *(uint32_t*)&h;
}

#define SWZ128(off) ((off) ^ (((off) >> 3) & 0x70))

__device__ __forceinline__ void ldsm_x4(uint32_t& r0, uint32_t& r1, uint32_t& r2, uint32_t& r3,
                                        uint32_t addr) {
    asm volatile("ldmatrix.sync.aligned.m8n8.x4.shared.b16 {%0,%1,%2,%3}, [%4];"
        : "=r"(r0), "=r"(r1), "=r"(r2), "=r"(r3) : "r"(addr));
}
__device__ __forceinline__ void mma16816(float* c, const uint32_t* a, const uint32_t* b) {
    asm volatile(
        "mma.sync.aligned.m16n8k16.row.col.f32.f16.f16.f32 "
        "{%0,%1,%2,%3}, {%4,%5,%6,%7}, {%8,%9}, {%0,%1,%2,%3};"
        : "+f"(c[0]), "+f"(c[1]), "+f"(c[2]), "+f"(c[3])
        : "r"(a[0]), "r"(a[1]), "r"(a[2]), "r"(a[3]), "r"(b[0]), "r"(b[1]));
}
__device__ __forceinline__ void cp_async16(uint32_t saddr, const void* gptr) {
    asm volatile("cp.async.cg.shared.global [%0], [%1], 16;" :: "r"(saddr), "l"(gptr) : "memory");
}
#define CP_COMMIT() asm volatile("cp.async.commit_group;" ::: "memory")
#define CP_WAIT(n)  asm volatile("cp.async.wait_group %0;" :: "n"(n) : "memory")

// ================================================================ kernel 1
// S -> fp16 hi/lo, [t][j] layout
__global__ void k_prep_S(const float* __restrict__ S) {
    int t = blockIdx.x, j = threadIdx.x;
    float v = S[t * DQ + j];
    __half h = __float2half_rn(v);
    __half l = __float2half_rn(v - __half2float(h));
    ((__half*)g_Sh4)[t * DQ + j] = h;
    ((__half*)g_Sl4)[t * DQ + j] = l;
}

// ================================================================ kernel 2
// per query: Qaug(fp16) = [q (128) | q@S^T (128)]   (fp32 math)
__global__ void k_prep_query(const float* __restrict__ query, const float* __restrict__ S) {
    __shared__ float qs[DQ];
    int q = blockIdx.x, t = threadIdx.x;
    qs[t] = query[q * DQ + t];
    __syncthreads();
    float acc = 0.0f;
    const float* srow = S + t * DQ;
    #pragma unroll 8
    for (int j = 0; j < DQ; j++) acc = fmaf(qs[j], srow[j], acc);
    __half* Qa = (__half*)g_Qaug4 + (size_t)q * KH;
    Qa[t]       = __float2half_rn(qs[t]);
    Qa[128 + t] = __float2half_rn(acc);
}

// ================================================================ kernel 3
// PERSISTENT fused key prep. 296 CTAs (2/SM), 256 thr, loop over 64-key tiles.
//  S hi/lo staged ONCE per CTA. Keys for tile t+GRID register-prefetched under
//  tile t's MMA phase. Per tile:
//   phase 1: norms, quantize, mse fp16 -> Kaug; residual hi/lo fp16 -> smem
//   phase 2: P = R @ S^T via 3-term fp16 HMMA split; signs -> smem -> coalesced Kaug
#define PITCHB 272
#define SM_AH  0
#define SM_AL  (64 * PITCHB)                  // 17408
#define SM_SH  (2 * 64 * PITCHB)              // 34816
#define SM_SL  (SM_SH + 128 * PITCHB)         // 69632
#define SM_CS  (SM_SL + 128 * PITCHB)         // 104448
#define PF_SMEM (SM_CS + 256)                 // 104704
#define PREP_GRID 296
#define NTILES (NKEY / 64)
__global__ void __launch_bounds__(256, 2) k_prep_keys(const float* __restrict__ keys,
                                                      const float* __restrict__ cb) {
    extern __shared__ char sm[];
    uint32_t sb = smem_u32(sm);
    float* cs = (float*)(sm + SM_CS);
    int tid = threadIdx.x, wid = tid >> 5, lane = tid & 31;

    // ---- stage S hi/lo once
    for (int i = tid; i < 2048; i += 256) {
        int t = i >> 4, u = i & 15;
        cp_async16(sb + SM_SH + t * PITCHB + u * 16, g_Sh4 + i);
        cp_async16(sb + SM_SL + t * PITCHB + u * 16, g_Sl4 + i);
    }
    CP_COMMIT();

    float c0 = cb[0], c1 = cb[1], c2 = cb[2], c3 = cb[3];
    float t01 = 0.5f * (c0 + c1), t12 = 0.5f * (c1 + c2), t23 = 0.5f * (c2 + c3);

    // thread roles
    int row = tid >> 2, qtr = tid & 3;                  // phase 1
    int wm = wid >> 2, wn = wid & 3;                    // phase 2: 2(M) x 4(N)
    int rowA = (lane & 7) + ((lane >> 3) & 1) * 8;
    int byteA = (lane >> 4) * 16;
    int rowB = (lane & 7) + (lane >> 4) * 8;
    int byteB = ((lane >> 3) & 1) * 16;
    int tq = lane >> 2, tn2 = (lane & 3) * 2;

    // ---- preload first tile's keys into registers
    float4 kf[8];
    {
        int n0 = blockIdx.x * 64 + row;
        const float4* kp = (const float4*)(keys + (size_t)n0 * DQ + qtr * 32);
        #pragma unroll
        for (int g = 0; g < 8; g++) kf[g] = kp[g];
    }

    CP_WAIT(0);
    __syncthreads();

    for (int tile = blockIdx.x; tile < NTILES; tile += PREP_GRID) {
        int key0 = tile * 64;
        int n = key0 + row;

        // ---- phase 1 (keys already in kf)
        float ss = 0.0f;
        #pragma unroll
        for (int g = 0; g < 8; g++) {
            ss = fmaf(kf[g].x, kf[g].x, ss);
            ss = fmaf(kf[g].y, kf[g].y, ss);
            ss = fmaf(kf[g].z, kf[g].z, ss);
            ss = fmaf(kf[g].w, kf[g].w, ss);
        }
        ss += __shfl_xor_sync(0xffffffffu, ss, 1);
        ss += __shfl_xor_sync(0xffffffffu, ss, 2);
        float vn = sqrtf(ss);
        float inv = 1.0f / (vn + EPSV);

        float rs = 0.0f;
        uint32_t hwm[16], hwh[16], hwl[16];
        #pragma unroll
        for (int g = 0; g < 8; g++) {
            float xv[4] = {kf[g].x, kf[g].y, kf[g].z, kf[g].w};
            float rv[4], mv[4], lv[4];
            #pragma unroll
            for (int e = 0; e < 4; e++) {
                float x = xv[e] * inv;
                float xm = c0;
                if (x > t01) xm = c1;
                if (x > t12) xm = c2;
                if (x > t23) xm = c3;
                float r = x - xm;
                rs = fmaf(r, r, rs);
                mv[e] = xm * vn;
                __half rh = __float2half_rn(r);
                rv[e] = __half2float(rh);
                lv[e] = r - rv[e];
            }
            hwm[g * 2 + 0] = h2pack(mv[0], mv[1]);
            hwm[g * 2 + 1] = h2pack(mv[2], mv[3]);
            hwh[g * 2 + 0] = h2pack(rv[0], rv[1]);
            hwh[g * 2 + 1] = h2pack(rv[2], rv[3]);
            hwl[g * 2 + 0] = h2pack(lv[0], lv[1]);
            hwl[g * 2 + 1] = h2pack(lv[2], lv[3]);
        }
        {
            uint4* Ka = g_Kaug4 + (size_t)n * (KH / 8) + qtr * 4;
            #pragma unroll
            for (int w = 0; w < 4; w++)
                Ka[w] = make_uint4(hwm[w * 4 + 0], hwm[w * 4 + 1], hwm[w * 4 + 2], hwm[w * 4 + 3]);
        }
        {
            uint4* Ap = (uint4*)(sm + SM_AH + row * PITCHB + qtr * 64);
            uint4* Lp = (uint4*)(sm + SM_AL + row * PITCHB + qtr * 64);
            #pragma unroll
            for (int w = 0; w < 4; w++) {
                Ap[w] = make_uint4(hwh[w * 4 + 0], hwh[w * 4 + 1], hwh[w * 4 + 2], hwh[w * 4 + 3]);
                Lp[w] = make_uint4(hwl[w * 4 + 0], hwl[w * 4 + 1], hwl[w * 4 + 2], hwl[w * 4 + 3]);
            }
        }
        rs += __shfl_xor_sync(0xffffffffu, rs, 1);
        rs += __shfl_xor_sync(0xffffffffu, rs, 2);
        if (qtr == 0) cs[row] = sqrtf(rs) * SCALEC * vn;
        __syncthreads();

        // ---- register-prefetch next tile's keys (latency hidden by MMA below)
        {
            int ntile = tile + PREP_GRID;
            if (ntile < NTILES) {
                const float4* kp = (const float4*)(keys + (size_t)(ntile * 64 + row) * DQ + qtr * 32);
                #pragma unroll
                for (int g = 0; g < 8; g++) kf[g] = kp[g];
            }
        }

        // ---- phase 2: HMMA P[64 x 128] = R @ S^T, 3 segments
        float acc[2][4][4];
        #pragma unroll
        for (int i = 0; i < 2; i++)
            #pragma unroll
            for (int j = 0; j < 4; j++)
                #pragma unroll
                for (int r = 0; r < 4; r++) acc[i][j][r] = 0.0f;

        #pragma unroll
        for (int seg = 0; seg < 3; seg++) {
            uint32_t aB = sb + (seg == 2 ? SM_AL : SM_AH);
            uint32_t bB = sb + (seg == 1 ? SM_SL : SM_SH);
            #pragma unroll
            for (int k16 = 0; k16 < 8; k16++) {
                int kb = k16 * 32;
                uint32_t af[2][4], bf[2][4];
                #pragma unroll
                for (int im = 0; im < 2; im++)
                    ldsm_x4(af[im][0], af[im][1], af[im][2], af[im][3],
                            aB + (wm * 32 + im * 16 + rowA) * PITCHB + kb + byteA);
                #pragma unroll
                for (int pr = 0; pr < 2; pr++)
                    ldsm_x4(bf[pr][0], bf[pr][1], bf[pr][2], bf[pr][3],
                            bB + (wn * 32 + pr * 16 + rowB) * PITCHB + kb + byteB);
                #pragma unroll
                for (int im = 0; im < 2; im++)
                    #pragma unroll
                    for (int in = 0; in < 4; in++)
                        mma16816(acc[im][in], af[im], &bf[in >> 1][(in & 1) * 2]);
            }
        }
        __syncthreads();   // all A-tile ldsm reads done (same-wm warps share A rows)

        // ---- signs * c -> smem (reuse A-hi region), then coalesced to Kaug
        #pragma unroll
        for (int im = 0; im < 2; im++) {
            int r0 = wm * 32 + im * 16 + tq;
            float ca = cs[r0], cb2 = cs[r0 + 8];
            #pragma unroll
            for (int in = 0; in < 4; in++) {
                int t = wn * 32 + in * 8 + tn2;
                *(uint32_t*)(sm + SM_AH + r0 * PITCHB + t * 2) =
                    h2pack(acc[im][in][0] >= 0.0f ? ca : -ca,
                           acc[im][in][1] >= 0.0f ? ca : -ca);
                *(uint32_t*)(sm + SM_AH + (r0 + 8) * PITCHB + t * 2) =
                    h2pack(acc[im][in][2] >= 0.0f ? cb2 : -cb2,
                           acc[im][in][3] >= 0.0f ? cb2 : -cb2);
            }
        }
        __syncthreads();

        // 64 rows x 16 uint4 (256 B of signs per key) = 1024 uint4
        #pragma unroll
        for (int i = 0; i < 4; i++) {
            int idx = tid + i * 256;
            int r = idx >> 4, u = idx & 15;
            uint4 v = *(const uint4*)(sm + SM_AH + r * PITCHB + u * 16);
            g_Kaug4[(size_t)(key0 + r) * (KH / 8) + 16 + u] = v;
        }
        __syncthreads();   // before next tile's phase-1 smem writes
    }
}

// ================================================================ kernel 4
// out[512, 131072] = Qaug @ Kaug^T via mma.sync m16n8k16 fp16->fp32, K=256.
// PROVEN round-5 config (112.8 us): CTA 128(M) x 128(N), 256 thr, 8 warps =
// 2(M) x 4(N), warp tile 64x32, double-buffered cp.async.
#define GE_STAGE 32768             // A 16KB + B 16KB
#define GE_SMEM  (2 * GE_STAGE)
__global__ void __launch_bounds__(256) k_gemm(float* __restrict__ out) {
    extern __shared__ char sm[];
    uint32_t sb = smem_u32(sm);
    int tid = threadIdx.x, wid = tid >> 5, lane = tid & 31;
    int nstrip = blockIdx.x >> 2;       // N-major: 4 M-tiles adjacent share B via L2
    int mtile  = blockIdx.x & 3;
    int key0 = nstrip * TN;

    int wm = wid >> 2, wn = wid & 3;    // warp tile: rows wm*64.., cols wn*32..

    int rowA = (lane & 7) + ((lane >> 3) & 1) * 8;   // A frags
    int byteA = (lane >> 4) * 16;
    int rowB = (lane & 7) + (lane >> 4) * 8;         // B frags
    int byteB = ((lane >> 3) & 1) * 16;

    float acc[4][4][4];
    #pragma unroll
    for (int i = 0; i < 4; i++)
        #pragma unroll
        for (int j = 0; j < 4; j++)
            #pragma unroll
            for (int r = 0; r < 4; r++) acc[i][j][r] = 0.0f;

    const uint4* QA = g_Qaug4;
    const uint4* KA = g_Kaug4;

    // chunk c covers fp16 cols [c*64, c*64+64) = uint4 [c*8, c*8+8) of the 32/row
    #define PREFETCH(c, buf) do { \
        int col8_ = (c) * 8; \
        uint32_t base_ = sb + (buf) * GE_STAGE; \
        _Pragma("unroll") \
        for (int it_ = 0; it_ < 8; it_++) { \
            int idx_ = tid + it_ * 256; \
            int half_ = idx_ >> 10; \
            int w_ = idx_ & 1023; \
            int row_ = w_ >> 3, u_ = w_ & 7; \
            const uint4* gp_; \
            if (half_ == 0) gp_ = QA + (size_t)(mtile * TM + row_) * 32 + col8_ + u_; \
            else            gp_ = KA + (size_t)(key0 + row_) * 32 + col8_ + u_; \
            uint32_t off_ = ((uint32_t)(row_ >> 3) << 10) | ((uint32_t)(row_ & 7) << 7) | ((uint32_t)u_ << 4); \
            off_ = SWZ128(off_); \
            cp_async16(base_ + half_ * 16384 + off_, gp_); \
        } \
        CP_COMMIT(); \
    } while (0)

    PREFETCH(0, 0);

    for (int c = 0; c < NCHUNK; c++) {
        if (c + 1 < NCHUNK) { PREFETCH(c + 1, (c + 1) & 1); CP_WAIT(1); }
        else                { CP_WAIT(0); }
        __syncthreads();

        uint32_t aBase = sb + (c & 1) * GE_STAGE;
        uint32_t bBase = aBase + 16384;

        #pragma unroll
        for (int k16 = 0; k16 < 4; k16++) {
            int kb = k16 * 32;
            uint32_t af[4][4], bf[2][4];
            #pragma unroll
            for (int im = 0; im < 4; im++) {
                int r = wm * 64 + im * 16 + rowA;
                uint32_t off = ((uint32_t)(r >> 3) << 10) | ((uint32_t)(r & 7) << 7) |
                               (uint32_t)(kb + byteA);
                ldsm_x4(af[im][0], af[im][1], af[im][2], af[im][3], aBase + SWZ128(off));
            }
            #pragma unroll
            for (int pr = 0; pr < 2; pr++) {
                int r = wn * 32 + pr * 16 + rowB;
                uint32_t off = ((uint32_t)(r >> 3) << 10) | ((uint32_t)(r & 7) << 7) |
                               (uint32_t)(kb + byteB);
                ldsm_x4(bf[pr][0], bf[pr][1], bf[pr][2], bf[pr][3], bBase + SWZ128(off));
            }
            #pragma unroll
            for (int im = 0; im < 4; im++) {
                #pragma unroll
                for (int in = 0; in < 4; in++) {
                    mma16816(acc[im][in], af[im], &bf[in >> 1][(in & 1) * 2]);
                }
            }
        }
        __syncthreads();
    }

    // ---- epilogue: direct fp32 stores ----
    int tq = lane >> 2, tn2 = (lane & 3) * 2;
    #pragma unroll
    for (int im = 0; im < 4; im++) {
        #pragma unroll
        for (int in = 0; in < 4; in++) {
            int m = mtile * TM + wm * 64 + im * 16 + tq;
            int n = key0 + wn * 32 + in * 8 + tn2;
            float2 v0 = make_float2(acc[im][in][0], acc[im][in][1]);
            float2 v1 = make_float2(acc[im][in][2], acc[im][in][3]);
            *(float2*)(out + (size_t)m * NKEY + n) = v0;
            *(float2*)(out + (size_t)(m + 8) * NKEY + n) = v1;
        }
    }
    #undef PREFETCH
}

// ================================================================ launch
extern "C" void kernel_launch(void* const* d_in, const int* in_sizes, int n_in,
                              void* d_out, int out_size) {
    const float* query = (const float*)d_in[0];
    const float* keys  = (const float*)d_in[1];
    const float* cb    = (const float*)d_in[2];
    const float* S     = (const float*)d_in[3];
    float* out = (float*)d_out;

    static bool attr_done = false;
    if (!attr_done) {
        cudaFuncSetAttribute(k_prep_keys, cudaFuncAttributeMaxDynamicSharedMemorySize, PF_SMEM);
        cudaFuncSetAttribute(k_gemm, cudaFuncAttributeMaxDynamicSharedMemorySize, GE_SMEM);
        attr_done = true;
    }

    k_prep_S<<<DQ, DQ>>>(S);
    k_prep_query<<<QN, 128>>>(query, S);
    k_prep_keys<<<PREP_GRID, 256, PF_SMEM>>>(keys, cb);
    k_gemm<<<(NKEY / TN) * (QN / TM), 256, GE_SMEM>>>(out);
}

// round 11
// speedup vs baseline: 1.0151x; 1.0151x over previous
#include <cuda_runtime.h>
#include <cuda_bf16.h>
#include <cuda_fp16.h>
#include <cstdint>
#include <cstddef>

// ---------------------------------------------------------------- constants
#define DQ   128          // head dim d == projection dim m
#define QN   512          // queries
#define NKEY 131072       // keys
#define KH   256          // fp16 halves per augmented row: [0:128) mse*vn, [128:256) sign*c
#define NCHUNK 4          // 4 x 64-col K chunks (main gemm)
#define TM 128
#define TN 256
#define EPSV 1e-8f
// sqrt(pi/2)/128
#define SCALEC 0.009791516697777347f

// ---------------------------------------------------------------- scratch
__device__ uint4 g_Kaug4[(size_t)NKEY * KH / 8];        // 64 MB fp16
__device__ uint4 g_Qaug4[(size_t)QN * KH / 8];          // 256 KB fp16
__device__ uint4 g_Sh4[DQ * DQ / 8];                    // S hi fp16, [t][j]
__device__ uint4 g_Sl4[DQ * DQ / 8];                    // S lo fp16, [t][j]

// ---------------------------------------------------------------- ptx utils
__device__ __forceinline__ uint32_t smem_u32(const void* p) {
    uint32_t a;
    asm("{ .reg .u64 tmp; cvta.to.shared.u64 tmp, %1; cvt.u32.u64 %0, tmp; }" : "=r"(a) : "l"(p));
    return a;
}
__device__ __forceinline__ uint32_t h2pack(float a, float b) {
    __half2 h = __floats2half2_rn(a, b);   // a -> low half (memory-first)
    return *(uint32_t*)&h;
}

#define SWZ128(off) ((off) ^ (((off) >> 3) & 0x70))

__device__ __forceinline__ void ldsm_x4(uint32_t& r0, uint32_t& r1, uint32_t& r2, uint32_t& r3,
                                        uint32_t addr) {
    asm volatile("ldmatrix.sync.aligned.m8n8.x4.shared.b16 {%0,%1,%2,%3}, [%4];"
        : "=r"(r0), "=r"(r1), "=r"(r2), "=r"(r3) : "r"(addr));
}
__device__ __forceinline__ void mma16816(float* c, const uint32_t* a, const uint32_t* b) {
    asm volatile(
        "mma.sync.aligned.m16n8k16.row.col.f32.f16.f16.f32 "
        "{%0,%1,%2,%3}, {%4,%5,%6,%7}, {%8,%9}, {%0,%1,%2,%3};"
        : "+f"(c[0]), "+f"(c[1]), "+f"(c[2]), "+f"(c[3])
        : "r"(a[0]), "r"(a[1]), "r"(a[2]), "r"(a[3]), "r"(b[0]), "r"(b[1]));
}
__device__ __forceinline__ void cp_async16(uint32_t saddr, const void* gptr) {
    asm volatile("cp.async.cg.shared.global [%0], [%1], 16;" :: "r"(saddr), "l"(gptr) : "memory");
}
#define CP_COMMIT() asm volatile("cp.async.commit_group;" ::: "memory")
#define CP_WAIT(n)  asm volatile("cp.async.wait_group %0;" :: "n"(n) : "memory")

// ================================================================ kernel 1
// S -> fp16 hi/lo, [t][j] layout
__global__ void k_prep_S(const float* __restrict__ S) {
    int t = blockIdx.x, j = threadIdx.x;
    float v = S[t * DQ + j];
    __half h = __float2half_rn(v);
    __half l = __float2half_rn(v - __half2float(h));
    ((__half*)g_Sh4)[t * DQ + j] = h;
    ((__half*)g_Sl4)[t * DQ + j] = l;
}

// ================================================================ kernel 2
// per query: Qaug(fp16) = [q (128) | q@S^T (128)]   (fp32 math)
__global__ void k_prep_query(const float* __restrict__ query, const float* __restrict__ S) {
    __shared__ float qs[DQ];
    int q = blockIdx.x, t = threadIdx.x;
    qs[t] = query[q * DQ + t];
    __syncthreads();
    float acc = 0.0f;
    const float* srow = S + t * DQ;
    #pragma unroll 8
    for (int j = 0; j < DQ; j++) acc = fmaf(qs[j], srow[j], acc);
    __half* Qa = (__half*)g_Qaug4 + (size_t)q * KH;
    Qa[t]       = __float2half_rn(qs[t]);
    Qa[128 + t] = __float2half_rn(acc);
}

// ================================================================ kernel 3
// PERSISTENT fused key prep (round-8 proven version). 296 CTAs (2/SM), 256 thr.
//  S hi/lo staged ONCE per CTA. Per tile:
//   phase 1: norms, quantize, mse fp16 -> Kaug; residual hi/lo fp16 -> smem
//   phase 2: P = R @ S^T via 3-term fp16 HMMA split; signs -> smem -> coalesced Kaug
#define PITCHB 272
#define SM_AH  0
#define SM_AL  (64 * PITCHB)                  // 17408
#define SM_SH  (2 * 64 * PITCHB)              // 34816
#define SM_SL  (SM_SH + 128 * PITCHB)         // 69632
#define SM_CS  (SM_SL + 128 * PITCHB)         // 104448
#define PF_SMEM (SM_CS + 256)                 // 104704
#define PREP_GRID 296
__global__ void __launch_bounds__(256, 2) k_prep_keys(const float* __restrict__ keys,
                                                      const float* __restrict__ cb) {
    extern __shared__ char sm[];
    uint32_t sb = smem_u32(sm);
    float* cs = (float*)(sm + SM_CS);
    int tid = threadIdx.x, wid = tid >> 5, lane = tid & 31;

    // ---- stage S hi/lo once
    for (int i = tid; i < 2048; i += 256) {
        int t = i >> 4, u = i & 15;
        cp_async16(sb + SM_SH + t * PITCHB + u * 16, g_Sh4 + i);
        cp_async16(sb + SM_SL + t * PITCHB + u * 16, g_Sl4 + i);
    }
    CP_COMMIT();

    float c0 = cb[0], c1 = cb[1], c2 = cb[2], c3 = cb[3];
    float t01 = 0.5f * (c0 + c1), t12 = 0.5f * (c1 + c2), t23 = 0.5f * (c2 + c3);

    // thread roles
    int row = tid >> 2, qtr = tid & 3;                  // phase 1
    int wm = wid >> 2, wn = wid & 3;                    // phase 2: 2(M) x 4(N)
    int rowA = (lane & 7) + ((lane >> 3) & 1) * 8;
    int byteA = (lane >> 4) * 16;
    int rowB = (lane & 7) + (lane >> 4) * 8;
    int byteB = ((lane >> 3) & 1) * 16;
    int tq = lane >> 2, tn2 = (lane & 3) * 2;

    CP_WAIT(0);
    __syncthreads();

    for (int tile = blockIdx.x; tile < NKEY / 64; tile += PREP_GRID) {
        int key0 = tile * 64;
        int n = key0 + row;

        // ---- phase 1
        const float4* kp = (const float4*)(keys + (size_t)n * DQ + qtr * 32);
        float4 kf[8];
        float ss = 0.0f;
        #pragma unroll
        for (int g = 0; g < 8; g++) {
            kf[g] = kp[g];
            ss = fmaf(kf[g].x, kf[g].x, ss);
            ss = fmaf(kf[g].y, kf[g].y, ss);
            ss = fmaf(kf[g].z, kf[g].z, ss);
            ss = fmaf(kf[g].w, kf[g].w, ss);
        }
        ss += __shfl_xor_sync(0xffffffffu, ss, 1);
        ss += __shfl_xor_sync(0xffffffffu, ss, 2);
        float vn = sqrtf(ss);
        float inv = 1.0f / (vn + EPSV);

        float rs = 0.0f;
        uint32_t hwm[16], hwh[16], hwl[16];
        #pragma unroll
        for (int g = 0; g < 8; g++) {
            float xv[4] = {kf[g].x, kf[g].y, kf[g].z, kf[g].w};
            float rv[4], mv[4], lv[4];
            #pragma unroll
            for (int e = 0; e < 4; e++) {
                float x = xv[e] * inv;
                float xm = c0;
                if (x > t01) xm = c1;
                if (x > t12) xm = c2;
                if (x > t23) xm = c3;
                float r = x - xm;
                rs = fmaf(r, r, rs);
                mv[e] = xm * vn;
                __half rh = __float2half_rn(r);
                rv[e] = __half2float(rh);
                lv[e] = r - rv[e];
            }
            hwm[g * 2 + 0] = h2pack(mv[0], mv[1]);
            hwm[g * 2 + 1] = h2pack(mv[2], mv[3]);
            hwh[g * 2 + 0] = h2pack(rv[0], rv[1]);
            hwh[g * 2 + 1] = h2pack(rv[2], rv[3]);
            hwl[g * 2 + 0] = h2pack(lv[0], lv[1]);
            hwl[g * 2 + 1] = h2pack(lv[2], lv[3]);
        }
        {
            uint4* Ka = g_Kaug4 + (size_t)n * (KH / 8) + qtr * 4;
            #pragma unroll
            for (int w = 0; w < 4; w++)
                Ka[w] = make_uint4(hwm[w * 4 + 0], hwm[w * 4 + 1], hwm[w * 4 + 2], hwm[w * 4 + 3]);
        }
        {
            uint4* Ap = (uint4*)(sm + SM_AH + row * PITCHB + qtr * 64);
            uint4* Lp = (uint4*)(sm + SM_AL + row * PITCHB + qtr * 64);
            #pragma unroll
            for (int w = 0; w < 4; w++) {
                Ap[w] = make_uint4(hwh[w * 4 + 0], hwh[w * 4 + 1], hwh[w * 4 + 2], hwh[w * 4 + 3]);
                Lp[w] = make_uint4(hwl[w * 4 + 0], hwl[w * 4 + 1], hwl[w * 4 + 2], hwl[w * 4 + 3]);
            }
        }
        rs += __shfl_xor_sync(0xffffffffu, rs, 1);
        rs += __shfl_xor_sync(0xffffffffu, rs, 2);
        if (qtr == 0) cs[row] = sqrtf(rs) * SCALEC * vn;
        __syncthreads();

        // ---- phase 2: HMMA P[64 x 128] = R @ S^T, 3 segments
        float acc[2][4][4];
        #pragma unroll
        for (int i = 0; i < 2; i++)
            #pragma unroll
            for (int j = 0; j < 4; j++)
                #pragma unroll
                for (int r = 0; r < 4; r++) acc[i][j][r] = 0.0f;

        #pragma unroll
        for (int seg = 0; seg < 3; seg++) {
            uint32_t aB = sb + (seg == 2 ? SM_AL : SM_AH);
            uint32_t bB = sb + (seg == 1 ? SM_SL : SM_SH);
            #pragma unroll
            for (int k16 = 0; k16 < 8; k16++) {
                int kb = k16 * 32;
                uint32_t af[2][4], bf[2][4];
                #pragma unroll
                for (int im = 0; im < 2; im++)
                    ldsm_x4(af[im][0], af[im][1], af[im][2], af[im][3],
                            aB + (wm * 32 + im * 16 + rowA) * PITCHB + kb + byteA);
                #pragma unroll
                for (int pr = 0; pr < 2; pr++)
                    ldsm_x4(bf[pr][0], bf[pr][1], bf[pr][2], bf[pr][3],
                            bB + (wn * 32 + pr * 16 + rowB) * PITCHB + kb + byteB);
                #pragma unroll
                for (int im = 0; im < 2; im++)
                    #pragma unroll
                    for (int in = 0; in < 4; in++)
                        mma16816(acc[im][in], af[im], &bf[in >> 1][(in & 1) * 2]);
            }
        }
        __syncthreads();   // all A-tile ldsm reads done (same-wm warps share A rows)

        // ---- signs * c -> smem (reuse A-hi region), then coalesced to Kaug
        #pragma unroll
        for (int im = 0; im < 2; im++) {
            int r0 = wm * 32 + im * 16 + tq;
            float ca = cs[r0], cb2 = cs[r0 + 8];
            #pragma unroll
            for (int in = 0; in < 4; in++) {
                int t = wn * 32 + in * 8 + tn2;
                *(uint32_t*)(sm + SM_AH + r0 * PITCHB + t * 2) =
                    h2pack(acc[im][in][0] >= 0.0f ? ca : -ca,
                           acc[im][in][1] >= 0.0f ? ca : -ca);
                *(uint32_t*)(sm + SM_AH + (r0 + 8) * PITCHB + t * 2) =
                    h2pack(acc[im][in][2] >= 0.0f ? cb2 : -cb2,
                           acc[im][in][3] >= 0.0f ? cb2 : -cb2);
            }
        }
        __syncthreads();

        // 64 rows x 16 uint4 (256 B of signs per key) = 1024 uint4
        #pragma unroll
        for (int i = 0; i < 4; i++) {
            int idx = tid + i * 256;
            int r = idx >> 4, u = idx & 15;
            uint4 v = *(const uint4*)(sm + SM_AH + r * PITCHB + u * 16);
            g_Kaug4[(size_t)(key0 + r) * (KH / 8) + 16 + u] = v;
        }
        __syncthreads();   // before next tile's phase-1 smem writes
    }
}

// ================================================================ kernel 4
// out[512, 131072] = Qaug @ Kaug^T via mma.sync m16n8k16 fp16->fp32, K=256.
// CTA 128(M) x 256(N), 256 thr, 8 warps = 2(M) x 4(N), warp tile 64x64
// (8 ldsm per 32 MMA), double-buffered cp.async, 96 KB smem.
#define GE_STAGE 49152             // A 16KB + B 32KB
#define GE_SMEM  (2 * GE_STAGE)
__global__ void __launch_bounds__(256, 1) k_gemm(float* __restrict__ out) {
    extern __shared__ char sm[];
    uint32_t sb = smem_u32(sm);
    int tid = threadIdx.x, wid = tid >> 5, lane = tid & 31;
    int nstrip = blockIdx.x >> 2;       // N-major: 4 M-tiles adjacent share B via L2
    int mtile  = blockIdx.x & 3;
    int key0 = nstrip * TN;

    int wm = wid >> 2, wn = wid & 3;    // warp tile: rows wm*64.., cols wn*64..

    int rowA = (lane & 7) + ((lane >> 3) & 1) * 8;   // A frags
    int byteA = (lane >> 4) * 16;
    int rowB = (lane & 7) + (lane >> 4) * 8;         // B frags
    int byteB = ((lane >> 3) & 1) * 16;

    float acc[4][8][4];                 // im x in x 4
    #pragma unroll
    for (int i = 0; i < 4; i++)
        #pragma unroll
        for (int j = 0; j < 8; j++)
            #pragma unroll
            for (int r = 0; r < 4; r++) acc[i][j][r] = 0.0f;

    const uint4* QA = g_Qaug4;
    const uint4* KA = g_Kaug4;

    // chunk c covers fp16 cols [c*64, c*64+64) = uint4 [c*8, c*8+8) of 32/row
    // stage: A 1024 uint4 (128 rows) at base, B 2048 uint4 (256 rows) at +16KB
    #define PREFETCH(c, buf) do { \
        int col8_ = (c) * 8; \
        uint32_t base_ = sb + (buf) * GE_STAGE; \
        _Pragma("unroll") \
        for (int it_ = 0; it_ < 12; it_++) { \
            int idx_ = tid + it_ * 256; \
            const uint4* gp_; \
            uint32_t dst_; \
            if (idx_ < 1024) { \
                int row_ = idx_ >> 3, u_ = idx_ & 7; \
                gp_ = QA + (size_t)(mtile * TM + row_) * 32 + col8_ + u_; \
                uint32_t off_ = ((uint32_t)(row_ >> 3) << 10) | ((uint32_t)(row_ & 7) << 7) | ((uint32_t)u_ << 4); \
                dst_ = base_ + SWZ128(off_); \
            } else { \
                int w_ = idx_ - 1024; \
                int row_ = w_ >> 3, u_ = w_ & 7; \
                gp_ = KA + (size_t)(key0 + row_) * 32 + col8_ + u_; \
                uint32_t off_ = ((uint32_t)(row_ >> 3) << 10) | ((uint32_t)(row_ & 7) << 7) | ((uint32_t)u_ << 4); \
                dst_ = base_ + 16384 + SWZ128(off_); \
            } \
            cp_async16(dst_, gp_); \
        } \
        CP_COMMIT(); \
    } while (0)

    PREFETCH(0, 0);

    for (int c = 0; c < NCHUNK; c++) {
        if (c + 1 < NCHUNK) { PREFETCH(c + 1, (c + 1) & 1); CP_WAIT(1); }
        else                { CP_WAIT(0); }
        __syncthreads();

        uint32_t aBase = sb + (c & 1) * GE_STAGE;
        uint32_t bBase = aBase + 16384;

        #pragma unroll
        for (int k16 = 0; k16 < 4; k16++) {
            int kb = k16 * 32;
            uint32_t af[4][4], bf[4][4];
            #pragma unroll
            for (int im = 0; im < 4; im++) {
                int r = wm * 64 + im * 16 + rowA;
                uint32_t off = ((uint32_t)(r >> 3) << 10) | ((uint32_t)(r & 7) << 7) |
                               (uint32_t)(kb + byteA);
                ldsm_x4(af[im][0], af[im][1], af[im][2], af[im][3], aBase + SWZ128(off));
            }
            #pragma unroll
            for (int pr = 0; pr < 4; pr++) {
                int r = wn * 64 + pr * 16 + rowB;
                uint32_t off = ((uint32_t)(r >> 3) << 10) | ((uint32_t)(r & 7) << 7) |
                               (uint32_t)(kb + byteB);
                ldsm_x4(bf[pr][0], bf[pr][1], bf[pr][2], bf[pr][3], bBase + SWZ128(off));
            }
            #pragma unroll
            for (int im = 0; im < 4; im++) {
                #pragma unroll
                for (int in = 0; in < 8; in++) {
                    mma16816(acc[im][in], af[im], &bf[in >> 1][(in & 1) * 2]);
                }
            }
        }
        __syncthreads();
    }

    // ---- epilogue: direct fp32 stores ----
    int tq = lane >> 2, tn2 = (lane & 3) * 2;
    #pragma unroll
    for (int im = 0; im < 4; im++) {
        #pragma unroll
        for (int in = 0; in < 8; in++) {
            int m = mtile * TM + wm * 64 + im * 16 + tq;
            int n = key0 + wn * 64 + in * 8 + tn2;
            float2 v0 = make_float2(acc[im][in][0], acc[im][in][1]);
            float2 v1 = make_float2(acc[im][in][2], acc[im][in][3]);
            *(float2*)(out + (size_t)m * NKEY + n) = v0;
            *(float2*)(out + (size_t)(m + 8) * NKEY + n) = v1;
        }
    }
    #undef PREFETCH
}

// ================================================================ launch
extern "C" void kernel_launch(void* const* d_in, const int* in_sizes, int n_in,
                              void* d_out, int out_size) {
    const float* query = (const float*)d_in[0];
    const float* keys  = (const float*)d_in[1];
    const float* cb    = (const float*)d_in[2];
    const float* S     = (const float*)d_in[3];
    float* out = (float*)d_out;

    static bool attr_done = false;
    if (!attr_done) {
        cudaFuncSetAttribute(k_prep_keys, cudaFuncAttributeMaxDynamicSharedMemorySize, PF_SMEM);
        cudaFuncSetAttribute(k_gemm, cudaFuncAttributeMaxDynamicSharedMemorySize, GE_SMEM);
        attr_done = true;
    }

    k_prep_S<<<DQ, DQ>>>(S);
    k_prep_query<<<QN, 128>>>(query, S);
    k_prep_keys<<<PREP_GRID, 256, PF_SMEM>>>(keys, cb);
    k_gemm<<<(NKEY / TN) * (QN / TM), 256, GE_SMEM>>>(out);
}

// round 12
// speedup vs baseline: 1.1067x; 1.0902x over previous
#include <cuda_runtime.h>
#include <cuda_bf16.h>
#include <cuda_fp16.h>
#include <cstdint>
#include <cstddef>

// ---------------------------------------------------------------- constants
#define DQ   128          // head dim d == projection dim m
#define QN   512          // queries
#define NKEY 131072       // keys
#define KH   256          // fp16 halves per augmented row: [0:128) mse*vn, [128:256) sign*c
#define NCHUNK 4          // 4 x 64-col K chunks (main gemm)
#define TM 128
#define TN 128
#define EPSV 1e-8f
// sqrt(pi/2)/128
#define SCALEC 0.009791516697777347f

// ---------------------------------------------------------------- scratch
__device__ uint4 g_Kaug4[(size_t)NKEY * KH / 8];        // 64 MB fp16
__device__ uint4 g_Qaug4[(size_t)QN * KH / 8];          // 256 KB fp16
__device__ uint4 g_Sh4[DQ * DQ / 8];                    // S hi fp16, [t][j]
__device__ uint4 g_Sl4[DQ * DQ / 8];                    // S lo fp16, [t][j]

// ---------------------------------------------------------------- ptx utils
__device__ __forceinline__ uint32_t smem_u32(const void* p) {
    uint32_t a;
    asm("{ .reg .u64 tmp; cvta.to.shared.u64 tmp, %1; cvt.u32.u64 %0, tmp; }" : "=r"(a) : "l"(p));
    return a;
}
__device__ __forceinline__ uint32_t h2pack(float a, float b) {
    __half2 h = __floats2half2_rn(a, b);   // a -> low half (memory-first)
    return *(uint32_t*)&h;
}

#define SWZ128(off) ((off) ^ (((off) >> 3) & 0x70))

__device__ __forceinline__ void ldsm_x4(uint32_t& r0, uint32_t& r1, uint32_t& r2, uint32_t& r3,
                                        uint32_t addr) {
    asm volatile("ldmatrix.sync.aligned.m8n8.x4.shared.b16 {%0,%1,%2,%3}, [%4];"
        : "=r"(r0), "=r"(r1), "=r"(r2), "=r"(r3) : "r"(addr));
}
__device__ __forceinline__ void mma16816(float* c, const uint32_t* a, const uint32_t* b) {
    asm volatile(
        "mma.sync.aligned.m16n8k16.row.col.f32.f16.f16.f32 "
        "{%0,%1,%2,%3}, {%4,%5,%6,%7}, {%8,%9}, {%0,%1,%2,%3};"
        : "+f"(c[0]), "+f"(c[1]), "+f"(c[2]), "+f"(c[3])
        : "r"(a[0]), "r"(a[1]), "r"(a[2]), "r"(a[3]), "r"(b[0]), "r"(b[1]));
}
__device__ __forceinline__ void cp_async16(uint32_t saddr, const void* gptr) {
    asm volatile("cp.async.cg.shared.global [%0], [%1], 16;" :: "r"(saddr), "l"(gptr) : "memory");
}
#define CP_COMMIT() asm volatile("cp.async.commit_group;" ::: "memory")
#define CP_WAIT(n)  asm volatile("cp.async.wait_group %0;" :: "n"(n) : "memory")

// ================================================================ kernel 1
// S -> fp16 hi/lo, [t][j] layout
__global__ void k_prep_S(const float* __restrict__ S) {
    int t = blockIdx.x, j = threadIdx.x;
    float v = S[t * DQ + j];
    __half h = __float2half_rn(v);
    __half l = __float2half_rn(v - __half2float(h));
    ((__half*)g_Sh4)[t * DQ + j] = h;
    ((__half*)g_Sl4)[t * DQ + j] = l;
}

// ================================================================ kernel 2
// per query: Qaug(fp16) = [q (128) | q@S^T (128)]   (fp32 math)
__global__ void k_prep_query(const float* __restrict__ query, const float* __restrict__ S) {
    __shared__ float qs[DQ];
    int q = blockIdx.x, t = threadIdx.x;
    qs[t] = query[q * DQ + t];
    __syncthreads();
    float acc = 0.0f;
    const float* srow = S + t * DQ;
    #pragma unroll 8
    for (int j = 0; j < DQ; j++) acc = fmaf(qs[j], srow[j], acc);
    __half* Qa = (__half*)g_Qaug4 + (size_t)q * KH;
    Qa[t]       = __float2half_rn(qs[t]);
    Qa[128 + t] = __float2half_rn(acc);
}

// ================================================================ kernel 3
// PERSISTENT fused key prep (round-8 measured-best version, verbatim).
// 296 CTAs (2/SM), 256 thr, loop over 64-key tiles. S hi/lo staged once.
#define PITCHB 272
#define SM_AH  0
#define SM_AL  (64 * PITCHB)                  // 17408
#define SM_SH  (2 * 64 * PITCHB)              // 34816
#define SM_SL  (SM_SH + 128 * PITCHB)         // 69632
#define SM_CS  (SM_SL + 128 * PITCHB)         // 104448
#define PF_SMEM (SM_CS + 256)                 // 104704
#define PREP_GRID 296
__global__ void __launch_bounds__(256, 2) k_prep_keys(const float* __restrict__ keys,
                                                      const float* __restrict__ cb) {
    extern __shared__ char sm[];
    uint32_t sb = smem_u32(sm);
    float* cs = (float*)(sm + SM_CS);
    int tid = threadIdx.x, wid = tid >> 5, lane = tid & 31;

    // ---- stage S hi/lo once
    for (int i = tid; i < 2048; i += 256) {
        int t = i >> 4, u = i & 15;
        cp_async16(sb + SM_SH + t * PITCHB + u * 16, g_Sh4 + i);
        cp_async16(sb + SM_SL + t * PITCHB + u * 16, g_Sl4 + i);
    }
    CP_COMMIT();

    float c0 = cb[0], c1 = cb[1], c2 = cb[2], c3 = cb[3];
    float t01 = 0.5f * (c0 + c1), t12 = 0.5f * (c1 + c2), t23 = 0.5f * (c2 + c3);

    // thread roles
    int row = tid >> 2, qtr = tid & 3;                  // phase 1
    int wm = wid >> 2, wn = wid & 3;                    // phase 2: 2(M) x 4(N)
    int rowA = (lane & 7) + ((lane >> 3) & 1) * 8;
    int byteA = (lane >> 4) * 16;
    int rowB = (lane & 7) + (lane >> 4) * 8;
    int byteB = ((lane >> 3) & 1) * 16;
    int tq = lane >> 2, tn2 = (lane & 3) * 2;

    CP_WAIT(0);
    __syncthreads();

    for (int tile = blockIdx.x; tile < NKEY / 64; tile += PREP_GRID) {
        int key0 = tile * 64;
        int n = key0 + row;

        // ---- phase 1
        const float4* kp = (const float4*)(keys + (size_t)n * DQ + qtr * 32);
        float4 kf[8];
        float ss = 0.0f;
        #pragma unroll
        for (int g = 0; g < 8; g++) {
            kf[g] = kp[g];
            ss = fmaf(kf[g].x, kf[g].x, ss);
            ss = fmaf(kf[g].y, kf[g].y, ss);
            ss = fmaf(kf[g].z, kf[g].z, ss);
            ss = fmaf(kf[g].w, kf[g].w, ss);
        }
        ss += __shfl_xor_sync(0xffffffffu, ss, 1);
        ss += __shfl_xor_sync(0xffffffffu, ss, 2);
        float vn = sqrtf(ss);
        float inv = 1.0f / (vn + EPSV);

        float rs = 0.0f;
        uint32_t hwm[16], hwh[16], hwl[16];
        #pragma unroll
        for (int g = 0; g < 8; g++) {
            float xv[4] = {kf[g].x, kf[g].y, kf[g].z, kf[g].w};
            float rv[4], mv[4], lv[4];
            #pragma unroll
            for (int e = 0; e < 4; e++) {
                float x = xv[e] * inv;
                float xm = c0;
                if (x > t01) xm = c1;
                if (x > t12) xm = c2;
                if (x > t23) xm = c3;
                float r = x - xm;
                rs = fmaf(r, r, rs);
                mv[e] = xm * vn;
                __half rh = __float2half_rn(r);
                rv[e] = __half2float(rh);
                lv[e] = r - rv[e];
            }
            hwm[g * 2 + 0] = h2pack(mv[0], mv[1]);
            hwm[g * 2 + 1] = h2pack(mv[2], mv[3]);
            hwh[g * 2 + 0] = h2pack(rv[0], rv[1]);
            hwh[g * 2 + 1] = h2pack(rv[2], rv[3]);
            hwl[g * 2 + 0] = h2pack(lv[0], lv[1]);
            hwl[g * 2 + 1] = h2pack(lv[2], lv[3]);
        }
        {
            uint4* Ka = g_Kaug4 + (size_t)n * (KH / 8) + qtr * 4;
            #pragma unroll
            for (int w = 0; w < 4; w++)
                Ka[w] = make_uint4(hwm[w * 4 + 0], hwm[w * 4 + 1], hwm[w * 4 + 2], hwm[w * 4 + 3]);
        }
        {
            uint4* Ap = (uint4*)(sm + SM_AH + row * PITCHB + qtr * 64);
            uint4* Lp = (uint4*)(sm + SM_AL + row * PITCHB + qtr * 64);
            #pragma unroll
            for (int w = 0; w < 4; w++) {
                Ap[w] = make_uint4(hwh[w * 4 + 0], hwh[w * 4 + 1], hwh[w * 4 + 2], hwh[w * 4 + 3]);
                Lp[w] = make_uint4(hwl[w * 4 + 0], hwl[w * 4 + 1], hwl[w * 4 + 2], hwl[w * 4 + 3]);
            }
        }
        rs += __shfl_xor_sync(0xffffffffu, rs, 1);
        rs += __shfl_xor_sync(0xffffffffu, rs, 2);
        if (qtr == 0) cs[row] = sqrtf(rs) * SCALEC * vn;
        __syncthreads();

        // ---- phase 2: HMMA P[64 x 128] = R @ S^T, 3 segments
        float acc[2][4][4];
        #pragma unroll
        for (int i = 0; i < 2; i++)
            #pragma unroll
            for (int j = 0; j < 4; j++)
                #pragma unroll
                for (int r = 0; r < 4; r++) acc[i][j][r] = 0.0f;

        #pragma unroll
        for (int seg = 0; seg < 3; seg++) {
            uint32_t aB = sb + (seg == 2 ? SM_AL : SM_AH);
            uint32_t bB = sb + (seg == 1 ? SM_SL : SM_SH);
            #pragma unroll
            for (int k16 = 0; k16 < 8; k16++) {
                int kb = k16 * 32;
                uint32_t af[2][4], bf[2][4];
                #pragma unroll
                for (int im = 0; im < 2; im++)
                    ldsm_x4(af[im][0], af[im][1], af[im][2], af[im][3],
                            aB + (wm * 32 + im * 16 + rowA) * PITCHB + kb + byteA);
                #pragma unroll
                for (int pr = 0; pr < 2; pr++)
                    ldsm_x4(bf[pr][0], bf[pr][1], bf[pr][2], bf[pr][3],
                            bB + (wn * 32 + pr * 16 + rowB) * PITCHB + kb + byteB);
                #pragma unroll
                for (int im = 0; im < 2; im++)
                    #pragma unroll
                    for (int in = 0; in < 4; in++)
                        mma16816(acc[im][in], af[im], &bf[in >> 1][(in & 1) * 2]);
            }
        }
        __syncthreads();   // all A-tile ldsm reads done (same-wm warps share A rows)

        // ---- signs * c -> smem (reuse A-hi region), then coalesced to Kaug
        #pragma unroll
        for (int im = 0; im < 2; im++) {
            int r0 = wm * 32 + im * 16 + tq;
            float ca = cs[r0], cb2 = cs[r0 + 8];
            #pragma unroll
            for (int in = 0; in < 4; in++) {
                int t = wn * 32 + in * 8 + tn2;
                *(uint32_t*)(sm + SM_AH + r0 * PITCHB + t * 2) =
                    h2pack(acc[im][in][0] >= 0.0f ? ca : -ca,
                           acc[im][in][1] >= 0.0f ? ca : -ca);
                *(uint32_t*)(sm + SM_AH + (r0 + 8) * PITCHB + t * 2) =
                    h2pack(acc[im][in][2] >= 0.0f ? cb2 : -cb2,
                           acc[im][in][3] >= 0.0f ? cb2 : -cb2);
            }
        }
        __syncthreads();

        // 64 rows x 16 uint4 (256 B of signs per key) = 1024 uint4
        #pragma unroll
        for (int i = 0; i < 4; i++) {
            int idx = tid + i * 256;
            int r = idx >> 4, u = idx & 15;
            uint4 v = *(const uint4*)(sm + SM_AH + r * PITCHB + u * 16);
            g_Kaug4[(size_t)(key0 + r) * (KH / 8) + 16 + u] = v;
        }
        __syncthreads();   // before next tile's phase-1 smem writes
    }
}

// ================================================================ kernel 4
// out[512, 131072] = Qaug @ Kaug^T via mma.sync m16n8k16 fp16->fp32, K=256.
// PROVEN config (112.0 us, measured twice): CTA 128(M) x 128(N), 256 thr,
// 8 warps = 2(M) x 4(N), warp tile 64x32, double-buffered cp.async, 2 CTAs/SM.
#define GE_STAGE 32768             // A 16KB + B 16KB
#define GE_SMEM  (2 * GE_STAGE)
__global__ void __launch_bounds__(256) k_gemm(float* __restrict__ out) {
    extern __shared__ char sm[];
    uint32_t sb = smem_u32(sm);
    int tid = threadIdx.x, wid = tid >> 5, lane = tid & 31;
    int nstrip = blockIdx.x >> 2;       // N-major: 4 M-tiles adjacent share B via L2
    int mtile  = blockIdx.x & 3;
    int key0 = nstrip * TN;

    int wm = wid >> 2, wn = wid & 3;    // warp tile: rows wm*64.., cols wn*32..

    int rowA = (lane & 7) + ((lane >> 3) & 1) * 8;   // A frags
    int byteA = (lane >> 4) * 16;
    int rowB = (lane & 7) + (lane >> 4) * 8;         // B frags
    int byteB = ((lane >> 3) & 1) * 16;

    float acc[4][4][4];
    #pragma unroll
    for (int i = 0; i < 4; i++)
        #pragma unroll
        for (int j = 0; j < 4; j++)
            #pragma unroll
            for (int r = 0; r < 4; r++) acc[i][j][r] = 0.0f;

    const uint4* QA = g_Qaug4;
    const uint4* KA = g_Kaug4;

    // chunk c covers fp16 cols [c*64, c*64+64) = uint4 [c*8, c*8+8) of the 32/row
    #define PREFETCH(c, buf) do { \
        int col8_ = (c) * 8; \
        uint32_t base_ = sb + (buf) * GE_STAGE; \
        _Pragma("unroll") \
        for (int it_ = 0; it_ < 8; it_++) { \
            int idx_ = tid + it_ * 256; \
            int half_ = idx_ >> 10; \
            int w_ = idx_ & 1023; \
            int row_ = w_ >> 3, u_ = w_ & 7; \
            const uint4* gp_; \
            if (half_ == 0) gp_ = QA + (size_t)(mtile * TM + row_) * 32 + col8_ + u_; \
            else            gp_ = KA + (size_t)(key0 + row_) * 32 + col8_ + u_; \
            uint32_t off_ = ((uint32_t)(row_ >> 3) << 10) | ((uint32_t)(row_ & 7) << 7) | ((uint32_t)u_ << 4); \
            off_ = SWZ128(off_); \
            cp_async16(base_ + half_ * 16384 + off_, gp_); \
        } \
        CP_COMMIT(); \
    } while (0)

    PREFETCH(0, 0);

    for (int c = 0; c < NCHUNK; c++) {
        if (c + 1 < NCHUNK) { PREFETCH(c + 1, (c + 1) & 1); CP_WAIT(1); }
        else                { CP_WAIT(0); }
        __syncthreads();

        uint32_t aBase = sb + (c & 1) * GE_STAGE;
        uint32_t bBase = aBase + 16384;

        #pragma unroll
        for (int k16 = 0; k16 < 4; k16++) {
            int kb = k16 * 32;
            uint32_t af[4][4], bf[2][4];
            #pragma unroll
            for (int im = 0; im < 4; im++) {
                int r = wm * 64 + im * 16 + rowA;
                uint32_t off = ((uint32_t)(r >> 3) << 10) | ((uint32_t)(r & 7) << 7) |
                               (uint32_t)(kb + byteA);
                ldsm_x4(af[im][0], af[im][1], af[im][2], af[im][3], aBase + SWZ128(off));
            }
            #pragma unroll
            for (int pr = 0; pr < 2; pr++) {
                int r = wn * 32 + pr * 16 + rowB;
                uint32_t off = ((uint32_t)(r >> 3) << 10) | ((uint32_t)(r & 7) << 7) |
                               (uint32_t)(kb + byteB);
                ldsm_x4(bf[pr][0], bf[pr][1], bf[pr][2], bf[pr][3], bBase + SWZ128(off));
            }
            #pragma unroll
            for (int im = 0; im < 4; im++) {
                #pragma unroll
                for (int in = 0; in < 4; in++) {
                    mma16816(acc[im][in], af[im], &bf[in >> 1][(in & 1) * 2]);
                }
            }
        }
        __syncthreads();
    }

    // ---- epilogue: direct fp32 stores ----
    int tq = lane >> 2, tn2 = (lane & 3) * 2;
    #pragma unroll
    for (int im = 0; im < 4; im++) {
        #pragma unroll
        for (int in = 0; in < 4; in++) {
            int m = mtile * TM + wm * 64 + im * 16 + tq;
            int n = key0 + wn * 32 + in * 8 + tn2;
            float2 v0 = make_float2(acc[im][in][0], acc[im][in][1]);
            float2 v1 = make_float2(acc[im][in][2], acc[im][in][3]);
            *(float2*)(out + (size_t)m * NKEY + n) = v0;
            *(float2*)(out + (size_t)(m + 8) * NKEY + n) = v1;
        }
    }
    #undef PREFETCH
}

// ================================================================ launch
extern "C" void kernel_launch(void* const* d_in, const int* in_sizes, int n_in,
                              void* d_out, int out_size) {
    const float* query = (const float*)d_in[0];
    const float* keys  = (const float*)d_in[1];
    const float* cb    = (const float*)d_in[2];
    const float* S     = (const float*)d_in[3];
    float* out = (float*)d_out;

    static bool attr_done = false;
    if (!attr_done) {
        cudaFuncSetAttribute(k_prep_keys, cudaFuncAttributeMaxDynamicSharedMemorySize, PF_SMEM);
        cudaFuncSetAttribute(k_gemm, cudaFuncAttributeMaxDynamicSharedMemorySize, GE_SMEM);
        attr_done = true;
    }

    k_prep_S<<<DQ, DQ>>>(S);
    k_prep_query<<<QN, 128>>>(query, S);
    k_prep_keys<<<PREP_GRID, 256, PF_SMEM>>>(keys, cb);
    k_gemm<<<(NKEY / TN) * (QN / TM), 256, GE_SMEM>>>(out);
}